// round 10
// baseline (speedup 1.0000x reference)
#include <cuda_runtime.h>
#include <cuda_fp16.h>
#include <math.h>

#define B_   4
#define LQ   1024
#define LK   2048
#define H_   8
#define HID  256
#define D_   32
#define TEMP_INV 10.0f
#define LOG2E 1.4426950408889634f

// ---------------- scratch (device globals; no allocations) ----------------
__device__ float g_G[H_ * 12 * 12];                 // per-head bilinear form (LOG2E-scaled)
__device__ float g_R[88 * HID];                     // fused Av_h @ Wo_h^T
__device__ float g_obias[HID];                      // bo + bv @ Wo^T
__device__ float g_Q[(size_t)B_ * H_ * 11 * LQ];    // Q-hat transposed [bh][c][q], c=0..10
__device__ float g_Kraw[(size_t)B_ * 11 * LK];      // raw key features transposed [b][j][k]
__device__ float g_kc[(size_t)B_ * H_ * LK];        // -beta*kn*LOG2E per head
__device__ __half g_lp[(size_t)B_ * LQ * LK];       // log2(clip(pi,1e-9)) in fp16
__device__ float g_cr[(size_t)B_ * LQ * 88];        // ctxRaw

__device__ __forceinline__ float sigmoidf_(float x) { return 1.f / (1.f + expf(-x)); }

__device__ __forceinline__ float ex2f(float x) {
    float r;
    asm("ex2.approx.ftz.f32 %0, %1;" : "=f"(r) : "f"(x));
    return r;
}

// ---------------- P0: fold weights into G_h, R, obias ----------------
__global__ void p0_params(const float* __restrict__ Wq_s, const float* __restrict__ bq_s,
                          const float* __restrict__ Wk_s, const float* __restrict__ bk_s,
                          const float* __restrict__ Wq_w, const float* __restrict__ bq_w,
                          const float* __restrict__ Wk_w, const float* __restrict__ bk_w,
                          const float* __restrict__ Wv,   const float* __restrict__ bv,
                          const float* __restrict__ Wo,   const float* __restrict__ bo,
                          const float* __restrict__ wb)
{
    int t = threadIdx.x;
    int blk = blockIdx.x;
    if (blk == H_) {
        float acc = bo[t];
        for (int u = 0; u < HID; u++) acc += bv[u] * Wo[t * HID + u];
        g_obias[t] = acc;
        return;
    }
    int h = blk;
    float alpha = sigmoidf_(wb[0]);
    float c1 = (1.f - alpha) / sqrtf((float)D_) * LOG2E;
    float c2 = 2.f * alpha * TEMP_INV * LOG2E;

    if (t < 144) {
        int r = t / 12, c = t % 12;
        float acc = 0.f;
        if (r < 8 && c < 8) {
            for (int d = 0; d < 32; d++) acc += Wq_s[(h*32+d)*8 + r] * Wk_s[(h*32+d)*8 + c];
            acc *= c1;
        } else if (r < 8 && c == 11) {
            for (int d = 0; d < 32; d++) acc += Wq_s[(h*32+d)*8 + r] * bk_s[h*32+d];
            acc *= c1;
        } else if (r >= 8 && r < 11 && c >= 8 && c < 11) {
            for (int d = 0; d < 32; d++) acc += Wq_w[(h*32+d)*3 + (r-8)] * Wk_w[(h*32+d)*3 + (c-8)];
            acc *= c2;
        } else if (r >= 8 && r < 11 && c == 11) {
            for (int d = 0; d < 32; d++) acc += Wq_w[(h*32+d)*3 + (r-8)] * bk_w[h*32+d];
            acc *= c2;
        } else if (r == 11 && c < 8) {
            for (int d = 0; d < 32; d++) acc += bq_s[h*32+d] * Wk_s[(h*32+d)*8 + c];
            acc *= c1;
        } else if (r == 11 && c >= 8 && c < 11) {
            for (int d = 0; d < 32; d++) acc += bq_w[h*32+d] * Wk_w[(h*32+d)*3 + (c-8)];
            acc *= c2;
        } else if (r == 11 && c == 11) {
            float a1 = 0.f, a2 = 0.f;
            for (int d = 0; d < 32; d++) {
                a1 += bq_s[h*32+d] * bk_s[h*32+d];
                a2 += bq_w[h*32+d] * bk_w[h*32+d];
            }
            acc = c1 * a1 + c2 * a2;
        }
        g_G[(h*12 + r)*12 + c] = acc;
    }
    float wo[32];
    #pragma unroll
    for (int d = 0; d < 32; d++) wo[d] = Wo[t * HID + h*32 + d];
    for (int j = 0; j < 11; j++) {
        float acc = 0.f;
        #pragma unroll
        for (int d = 0; d < 32; d++) acc += Wv[(h*32+d)*11 + j] * wo[d];
        g_R[(h*11 + j) * HID + t] = acc;
    }
}

// ---------------- P1q: build Q-hat, head-parallel (blockIdx.y = h) ----------------
__global__ void __launch_bounds__(128)
p1_q(const float* __restrict__ q_fp)
{
    __shared__ float Gs[144];
    int t = threadIdx.x;
    int h = blockIdx.y;
    for (int i = t; i < 144; i += 128) Gs[i] = g_G[h * 144 + i];
    __syncthreads();

    int idx = blockIdx.x * 128 + t;   // b*LQ + q
    int b = idx >> 10, q = idx & (LQ - 1);

    float x[11];
    #pragma unroll
    for (int j = 0; j < 11; j++) x[j] = q_fp[(size_t)idx * 11 + j];

    size_t base = ((size_t)(b * H_ + h) * 11) * LQ + q;
    #pragma unroll
    for (int c = 0; c < 11; c++) {
        float a = Gs[11*12 + c];
        #pragma unroll
        for (int r = 0; r < 11; r++) a += x[r] * Gs[r*12 + c];
        g_Q[base + (size_t)c * LQ] = a;
    }
}

// ---------------- P1k: raw K features + per-head kn, head-parallel (blockIdx.y = h) ----------------
__global__ void __launch_bounds__(128)
p1_k(const float* __restrict__ v_ret, const float* __restrict__ Wk_w,
     const float* __restrict__ bk_w, const float* __restrict__ wb)
{
    __shared__ float Ws[D_ * 3];
    __shared__ float Bs[D_];
    int t = threadIdx.x;
    int h = blockIdx.y;
    if (t < D_ * 3) Ws[t] = Wk_w[h * D_ * 3 + t];
    if (t < D_)     Bs[t] = bk_w[h * D_ + t];
    __syncthreads();

    float alpha = sigmoidf_(wb[0]);
    float beta2 = alpha * TEMP_INV * LOG2E;
    int idx = blockIdx.x * 128 + t;   // b*LK + k
    int b = idx >> 11, k = idx & (LK - 1);

    float x3[3];
    #pragma unroll
    for (int j = 0; j < 3; j++) x3[j] = v_ret[(size_t)idx * 11 + 8 + j];

    if (h == 0) {
        #pragma unroll
        for (int j = 0; j < 11; j++)
            g_Kraw[((size_t)b * 11 + j) * LK + k] = v_ret[(size_t)idx * 11 + j];
    }

    float kn = 0.f;
    #pragma unroll 4
    for (int d = 0; d < D_; d++) {
        float s = Bs[d];
        s += x3[0] * Ws[d*3 + 0];
        s += x3[1] * Ws[d*3 + 1];
        s += x3[2] * Ws[d*3 + 2];
        kn += s * s;
    }
    g_kc[(size_t)(b * H_ + h) * LK + k] = -beta2 * kn;
}

// ---------------- P2: log2 of transport mask -> fp16, once (shared by all heads) ----------------
__global__ void __launch_bounds__(256)
p_logpi(const float* __restrict__ pi)
{
    size_t i = ((size_t)blockIdx.x * 256 + threadIdx.x) * 4;
    float4 v = *(const float4*)(pi + i);
    __half2 h0 = __floats2half2_rn(__log2f(fmaxf(v.x, 1e-9f)),
                                   __log2f(fmaxf(v.y, 1e-9f)));
    __half2 h1 = __floats2half2_rn(__log2f(fmaxf(v.z, 1e-9f)),
                                   __log2f(fmaxf(v.w, 1e-9f)));
    uint2 pk;
    pk.x = *(unsigned*)&h0;
    pk.y = *(unsigned*)&h1;
    *(uint2*)(g_lp + i) = pk;
}

// ---------------- main attention kernel: R5 schedule, occupancy 3 via reg cap ----------------
// 256 threads = 16 tx (4 keys) x 16 ty (4 rows). BM=BN=64. Double-buffered K tile.
__global__ void __launch_bounds__(256, 3)
attn_kernel()
{
    __shared__ float Qs[11][64];        // Q-tilde rows 0..10
    __shared__ float Ks[2][12][64];     // rows 0..10: raw key feats (= V), row 11: kc

    int t = threadIdx.x;
    int tx = t & 15, ty = t >> 4;
    int h = blockIdx.x, qt = blockIdx.y, b = blockIdx.z;
    int bh = b * H_ + h;
    int q0 = qt * 64;

    if (t < 176) {
        int c = t >> 4, col4 = (t & 15) * 4;
        *(float4*)&Qs[c][col4] =
            *(const float4*)&g_Q[((size_t)bh * 11 + c) * LQ + q0 + col4];
    }
    if (t < 192) {
        int c = t >> 4, col4 = (t & 15) * 4;
        const float* src = (c < 11)
            ? &g_Kraw[((size_t)b * 11 + c) * LK + col4]
            : &g_kc[(size_t)bh * LK + col4];
        *(float4*)&Ks[0][c][col4] = *(const float4*)src;
    }

    float O[4][11];
    float l[4];
    #pragma unroll
    for (int i = 0; i < 4; i++) {
        l[i] = 0.f;
        #pragma unroll
        for (int c = 0; c < 11; c++) O[i][c] = 0.f;
    }

    const __half* lpP = g_lp + ((size_t)(b * LQ + q0 + ty * 4)) * LK + tx * 4;

    __syncthreads();

    for (int kt = 0; kt < 32; kt++) {
        int cur = kt & 1;
        int k0 = kt * 64;

        // prefetch log2(pi) tile in fp16 (consumed after QK — L2 latency hidden)
        uint2 r0 = *(const uint2*)(lpP + k0);
        uint2 r1 = *(const uint2*)(lpP + (size_t)LK + k0);
        uint2 r2 = *(const uint2*)(lpP + (size_t)2 * LK + k0);
        uint2 r3 = *(const uint2*)(lpP + (size_t)3 * LK + k0);

        // stage next K tile into the other buffer
        if (kt < 31 && t < 192) {
            int c = t >> 4, col4 = (t & 15) * 4;
            const float* src = (c < 11)
                ? &g_Kraw[((size_t)b * 11 + c) * LK + k0 + 64 + col4]
                : &g_kc[(size_t)bh * LK + k0 + 64 + col4];
            *(float4*)&Ks[cur ^ 1][c][col4] = *(const float4*)src;
        }

        // ---- QK: S = Qt . k_raw  (inner dim 11), kc folded into first FMA ----
        float S[4][4];
        {
            float4 kc4 = *(const float4*)&Ks[cur][11][tx * 4];
            float kcv[4] = {kc4.x, kc4.y, kc4.z, kc4.w};
            float4 a4 = *(const float4*)&Qs[0][ty * 4];
            float4 b4 = *(const float4*)&Ks[cur][0][tx * 4];
            float av[4] = {a4.x, a4.y, a4.z, a4.w};
            float bw[4] = {b4.x, b4.y, b4.z, b4.w};
            #pragma unroll
            for (int i = 0; i < 4; i++)
                #pragma unroll
                for (int j = 0; j < 4; j++) S[i][j] = av[i] * bw[j] + kcv[j];
        }
        #pragma unroll
        for (int kk = 1; kk < 11; kk++) {
            float4 a4 = *(const float4*)&Qs[kk][ty * 4];
            float4 b4 = *(const float4*)&Ks[cur][kk][tx * 4];
            float av[4] = {a4.x, a4.y, a4.z, a4.w};
            float bw[4] = {b4.x, b4.y, b4.z, b4.w};
            #pragma unroll
            for (int i = 0; i < 4; i++)
                #pragma unroll
                for (int j = 0; j < 4; j++) S[i][j] += av[i] * bw[j];
        }

        // ---- + log2(pi), exp2, accumulate l ----
        {
            float2 p00 = __half22float2(*(__half2*)&r0.x);
            float2 p01 = __half22float2(*(__half2*)&r0.y);
            float2 p10 = __half22float2(*(__half2*)&r1.x);
            float2 p11 = __half22float2(*(__half2*)&r1.y);
            float2 p20 = __half22float2(*(__half2*)&r2.x);
            float2 p21 = __half22float2(*(__half2*)&r2.y);
            float2 p30 = __half22float2(*(__half2*)&r3.x);
            float2 p31 = __half22float2(*(__half2*)&r3.y);
            float pr[4][4] = {{p00.x, p00.y, p01.x, p01.y},
                              {p10.x, p10.y, p11.x, p11.y},
                              {p20.x, p20.y, p21.x, p21.y},
                              {p30.x, p30.y, p31.x, p31.y}};
            #pragma unroll
            for (int i = 0; i < 4; i++) {
                #pragma unroll
                for (int j = 0; j < 4; j++) {
                    S[i][j] = ex2f(S[i][j] + pr[i][j]);
                    l[i] += S[i][j];
                }
            }
        }

        // ---- PV: O += P . v_raw  (V tile == K tile rows 0..10) ----
        #pragma unroll
        for (int c = 0; c < 11; c++) {
            float4 v4 = *(const float4*)&Ks[cur][c][tx * 4];
            float vv[4] = {v4.x, v4.y, v4.z, v4.w};
            #pragma unroll
            for (int i = 0; i < 4; i++) {
                O[i][c] += S[i][0] * vv[0] + S[i][1] * vv[1]
                         + S[i][2] * vv[2] + S[i][3] * vv[3];
            }
        }

        __syncthreads();
    }

    // ---- reduce across the 16 tx lanes, normalize, store ----
    #pragma unroll
    for (int i = 0; i < 4; i++) {
        l[i] += __shfl_xor_sync(0xffffffffu, l[i], 1);
        l[i] += __shfl_xor_sync(0xffffffffu, l[i], 2);
        l[i] += __shfl_xor_sync(0xffffffffu, l[i], 4);
        l[i] += __shfl_xor_sync(0xffffffffu, l[i], 8);
        #pragma unroll
        for (int c = 0; c < 11; c++) {
            O[i][c] += __shfl_xor_sync(0xffffffffu, O[i][c], 1);
            O[i][c] += __shfl_xor_sync(0xffffffffu, O[i][c], 2);
            O[i][c] += __shfl_xor_sync(0xffffffffu, O[i][c], 4);
            O[i][c] += __shfl_xor_sync(0xffffffffu, O[i][c], 8);
        }
    }

    if (tx == 0) {
        #pragma unroll
        for (int i = 0; i < 4; i++) {
            float inv = 1.0f / l[i];
            size_t base = ((size_t)(b * LQ + q0 + ty * 4 + i)) * 88 + h * 11;
            #pragma unroll
            for (int c = 0; c < 11; c++) g_cr[base + c] = O[i][c] * inv;
        }
    }
}

// ---------------- epilogue: out = ctxRaw(4096x88) @ R(88x256) + obias ----------------
__global__ void __launch_bounds__(256)
epilogue_kernel(float* __restrict__ out)
{
    __shared__ float crsT[88][32];
    int t = threadIdx.x;
    int row0 = blockIdx.x * 32;

    for (int i = t; i < 32 * 88; i += 256) {
        int r = i / 88, j = i % 88;
        crsT[j][r] = g_cr[(size_t)(row0 + r) * 88 + j];
    }
    __syncthreads();

    float acc[32];
    #pragma unroll
    for (int r = 0; r < 32; r++) acc[r] = 0.f;

    #pragma unroll 4
    for (int j = 0; j < 88; j++) {
        float rv = g_R[j * HID + t];
        #pragma unroll
        for (int r = 0; r < 32; r += 4) {
            float4 cv = *(const float4*)&crsT[j][r];
            acc[r]     += cv.x * rv;
            acc[r + 1] += cv.y * rv;
            acc[r + 2] += cv.z * rv;
            acc[r + 3] += cv.w * rv;
        }
    }

    float ob = g_obias[t];
    for (int r = 0; r < 32; r++)
        out[(size_t)(row0 + r) * HID + t] = acc[r] + ob;
}

// ---------------- launch ----------------
extern "C" void kernel_launch(void* const* d_in, const int* in_sizes, int n_in,
                              void* d_out, int out_size)
{
    const float* q_fp  = (const float*)d_in[0];
    const float* v_ret = (const float*)d_in[1];
    const float* pi    = (const float*)d_in[2];
    const float* Wq_s  = (const float*)d_in[3];
    const float* bq_s  = (const float*)d_in[4];
    const float* Wk_s  = (const float*)d_in[5];
    const float* bk_s  = (const float*)d_in[6];
    const float* Wq_w  = (const float*)d_in[7];
    const float* bq_w  = (const float*)d_in[8];
    const float* Wk_w  = (const float*)d_in[9];
    const float* bk_w  = (const float*)d_in[10];
    const float* Wv    = (const float*)d_in[11];
    const float* bv    = (const float*)d_in[12];
    const float* Wo    = (const float*)d_in[13];
    const float* bo    = (const float*)d_in[14];
    const float* wb    = (const float*)d_in[15];
    float* out = (float*)d_out;

    p0_params<<<H_ + 1, 256>>>(Wq_s, bq_s, Wk_s, bk_s, Wq_w, bq_w, Wk_w, bk_w,
                               Wv, bv, Wo, bo, wb);
    dim3 gq((B_ * LQ) / 128, H_);
    p1_q<<<gq, 128>>>(q_fp);
    dim3 gk((B_ * LK) / 128, H_);
    p1_k<<<gk, 128>>>(v_ret, Wk_w, bk_w, wb);
    p_logpi<<<(B_ * LQ * LK) / 1024, 256>>>(pi);
    dim3 g(H_, LQ / 64, B_);
    attn_kernel<<<g, 256>>>();
    epilogue_kernel<<<(B_ * LQ) / 32, 256>>>(out);
}

// round 11
// speedup vs baseline: 1.4517x; 1.4517x over previous
#include <cuda_runtime.h>
#include <math.h>

#define B_   4
#define LQ   1024
#define LK   2048
#define H_   8
#define HID  256
#define D_   32
#define TEMP_INV 10.0f
#define LOG2E 1.4426950408889634f

// ---------------- scratch (device globals; no allocations) ----------------
__device__ float g_G[H_ * 12 * 12];                 // per-head bilinear form (LOG2E-scaled)
__device__ float g_R[88 * HID];                     // fused Av_h @ Wo_h^T
__device__ float g_obias[HID];                      // bo + bv @ Wo^T
__device__ float g_Q[(size_t)B_ * H_ * 11 * LQ];    // Q-hat transposed [bh][c][q], c=0..10
__device__ float g_Kraw[(size_t)B_ * 11 * LK];      // raw key features transposed [b][j][k]
__device__ float g_kc[(size_t)B_ * H_ * LK];        // -beta*kn*LOG2E per head
__device__ float g_cr[(size_t)B_ * LQ * 88];        // ctxRaw

__device__ __forceinline__ float sigmoidf_(float x) { return 1.f / (1.f + expf(-x)); }

__device__ __forceinline__ float ex2f(float x) {
    float r;
    asm("ex2.approx.ftz.f32 %0, %1;" : "=f"(r) : "f"(x));
    return r;
}
__device__ __forceinline__ float lg2p(float x) {
    return __log2f(fmaxf(x, 1e-9f));
}

// ---------------- P0: fold weights into G_h, R, obias ----------------
__global__ void p0_params(const float* __restrict__ Wq_s, const float* __restrict__ bq_s,
                          const float* __restrict__ Wk_s, const float* __restrict__ bk_s,
                          const float* __restrict__ Wq_w, const float* __restrict__ bq_w,
                          const float* __restrict__ Wk_w, const float* __restrict__ bk_w,
                          const float* __restrict__ Wv,   const float* __restrict__ bv,
                          const float* __restrict__ Wo,   const float* __restrict__ bo,
                          const float* __restrict__ wb)
{
    int t = threadIdx.x;
    int blk = blockIdx.x;
    if (blk == H_) {
        float acc = bo[t];
        for (int u = 0; u < HID; u++) acc += bv[u] * Wo[t * HID + u];
        g_obias[t] = acc;
        return;
    }
    int h = blk;
    float alpha = sigmoidf_(wb[0]);
    float c1 = (1.f - alpha) / sqrtf((float)D_) * LOG2E;
    float c2 = 2.f * alpha * TEMP_INV * LOG2E;

    if (t < 144) {
        int r = t / 12, c = t % 12;
        float acc = 0.f;
        if (r < 8 && c < 8) {
            for (int d = 0; d < 32; d++) acc += Wq_s[(h*32+d)*8 + r] * Wk_s[(h*32+d)*8 + c];
            acc *= c1;
        } else if (r < 8 && c == 11) {
            for (int d = 0; d < 32; d++) acc += Wq_s[(h*32+d)*8 + r] * bk_s[h*32+d];
            acc *= c1;
        } else if (r >= 8 && r < 11 && c >= 8 && c < 11) {
            for (int d = 0; d < 32; d++) acc += Wq_w[(h*32+d)*3 + (r-8)] * Wk_w[(h*32+d)*3 + (c-8)];
            acc *= c2;
        } else if (r >= 8 && r < 11 && c == 11) {
            for (int d = 0; d < 32; d++) acc += Wq_w[(h*32+d)*3 + (r-8)] * bk_w[h*32+d];
            acc *= c2;
        } else if (r == 11 && c < 8) {
            for (int d = 0; d < 32; d++) acc += bq_s[h*32+d] * Wk_s[(h*32+d)*8 + c];
            acc *= c1;
        } else if (r == 11 && c >= 8 && c < 11) {
            for (int d = 0; d < 32; d++) acc += bq_w[h*32+d] * Wk_w[(h*32+d)*3 + (c-8)];
            acc *= c2;
        } else if (r == 11 && c == 11) {
            float a1 = 0.f, a2 = 0.f;
            for (int d = 0; d < 32; d++) {
                a1 += bq_s[h*32+d] * bk_s[h*32+d];
                a2 += bq_w[h*32+d] * bk_w[h*32+d];
            }
            acc = c1 * a1 + c2 * a2;
        }
        g_G[(h*12 + r)*12 + c] = acc;
    }
    float wo[32];
    #pragma unroll
    for (int d = 0; d < 32; d++) wo[d] = Wo[t * HID + h*32 + d];
    for (int j = 0; j < 11; j++) {
        float acc = 0.f;
        #pragma unroll
        for (int d = 0; d < 32; d++) acc += Wv[(h*32+d)*11 + j] * wo[d];
        g_R[(h*11 + j) * HID + t] = acc;
    }
}

// ---------------- P1q: build Q-hat, head-parallel (blockIdx.y = h) ----------------
__global__ void __launch_bounds__(128)
p1_q(const float* __restrict__ q_fp)
{
    __shared__ float Gs[144];
    int t = threadIdx.x;
    int h = blockIdx.y;
    for (int i = t; i < 144; i += 128) Gs[i] = g_G[h * 144 + i];
    __syncthreads();

    int idx = blockIdx.x * 128 + t;   // b*LQ + q
    int b = idx >> 10, q = idx & (LQ - 1);

    float x[11];
    #pragma unroll
    for (int j = 0; j < 11; j++) x[j] = q_fp[(size_t)idx * 11 + j];

    size_t base = ((size_t)(b * H_ + h) * 11) * LQ + q;
    #pragma unroll
    for (int c = 0; c < 11; c++) {
        float a = Gs[11*12 + c];
        #pragma unroll
        for (int r = 0; r < 11; r++) a += x[r] * Gs[r*12 + c];
        g_Q[base + (size_t)c * LQ] = a;
    }
}

// ---------------- P1k: raw K features + per-head kn, head-parallel (blockIdx.y = h) ----------------
__global__ void __launch_bounds__(128)
p1_k(const float* __restrict__ v_ret, const float* __restrict__ Wk_w,
     const float* __restrict__ bk_w, const float* __restrict__ wb)
{
    __shared__ float Ws[D_ * 3];
    __shared__ float Bs[D_];
    int t = threadIdx.x;
    int h = blockIdx.y;
    if (t < D_ * 3) Ws[t] = Wk_w[h * D_ * 3 + t];
    if (t < D_)     Bs[t] = bk_w[h * D_ + t];
    __syncthreads();

    float alpha = sigmoidf_(wb[0]);
    float beta2 = alpha * TEMP_INV * LOG2E;
    int idx = blockIdx.x * 128 + t;   // b*LK + k
    int b = idx >> 11, k = idx & (LK - 1);

    float x3[3];
    #pragma unroll
    for (int j = 0; j < 3; j++) x3[j] = v_ret[(size_t)idx * 11 + 8 + j];

    if (h == 0) {
        #pragma unroll
        for (int j = 0; j < 11; j++)
            g_Kraw[((size_t)b * 11 + j) * LK + k] = v_ret[(size_t)idx * 11 + j];
    }

    float kn = 0.f;
    #pragma unroll 4
    for (int d = 0; d < D_; d++) {
        float s = Bs[d];
        s += x3[0] * Ws[d*3 + 0];
        s += x3[1] * Ws[d*3 + 1];
        s += x3[2] * Ws[d*3 + 2];
        kn += s * s;
    }
    g_kc[(size_t)(b * H_ + h) * LK + k] = -beta2 * kn;
}

// ---------------- main attention kernel: R9 schedule + fused log2(pi) ----------------
// 256 threads = 16 tx (4 keys) x 16 ty (4 rows). BM=BN=64. Double-buffered K tile.
__global__ void __launch_bounds__(256, 2)
attn_kernel(const float* __restrict__ pi)
{
    __shared__ float Qs[11][64];        // Q-tilde rows 0..10
    __shared__ float Ks[2][12][64];     // rows 0..10: raw key feats (= V), row 11: kc

    int t = threadIdx.x;
    int tx = t & 15, ty = t >> 4;
    int h = blockIdx.x, qt = blockIdx.y, b = blockIdx.z;
    int bh = b * H_ + h;
    int q0 = qt * 64;

    if (t < 176) {
        int c = t >> 4, col4 = (t & 15) * 4;
        *(float4*)&Qs[c][col4] =
            *(const float4*)&g_Q[((size_t)bh * 11 + c) * LQ + q0 + col4];
    }
    if (t < 192) {
        int c = t >> 4, col4 = (t & 15) * 4;
        const float* src = (c < 11)
            ? &g_Kraw[((size_t)b * 11 + c) * LK + col4]
            : &g_kc[(size_t)bh * LK + col4];
        *(float4*)&Ks[0][c][col4] = *(const float4*)src;
    }

    float O[4][11];
    float l[4];
    #pragma unroll
    for (int i = 0; i < 4; i++) {
        l[i] = 0.f;
        #pragma unroll
        for (int c = 0; c < 11; c++) O[i][c] = 0.f;
    }

    const float* piP = pi + ((size_t)(b * LQ + q0 + ty * 4)) * LK + tx * 4;

    __syncthreads();

    for (int kt = 0; kt < 32; kt++) {
        int cur = kt & 1;
        int k0 = kt * 64;

        // prefetch pi tile (fp32, L2-resident across the 8 heads; consumed after QK)
        float4 pv0 = *(const float4*)(piP + k0);
        float4 pv1 = *(const float4*)(piP + (size_t)LK + k0);
        float4 pv2 = *(const float4*)(piP + (size_t)2 * LK + k0);
        float4 pv3 = *(const float4*)(piP + (size_t)3 * LK + k0);

        // stage next K tile into the other buffer
        if (kt < 31 && t < 192) {
            int c = t >> 4, col4 = (t & 15) * 4;
            const float* src = (c < 11)
                ? &g_Kraw[((size_t)b * 11 + c) * LK + k0 + 64 + col4]
                : &g_kc[(size_t)bh * LK + k0 + 64 + col4];
            *(float4*)&Ks[cur ^ 1][c][col4] = *(const float4*)src;
        }

        // ---- QK: S = Qt . k_raw  (inner dim 11), kc folded into first FMA ----
        float S[4][4];
        {
            float4 kc4 = *(const float4*)&Ks[cur][11][tx * 4];
            float kcv[4] = {kc4.x, kc4.y, kc4.z, kc4.w};
            float4 a4 = *(const float4*)&Qs[0][ty * 4];
            float4 b4 = *(const float4*)&Ks[cur][0][tx * 4];
            float av[4] = {a4.x, a4.y, a4.z, a4.w};
            float bw[4] = {b4.x, b4.y, b4.z, b4.w};
            #pragma unroll
            for (int i = 0; i < 4; i++)
                #pragma unroll
                for (int j = 0; j < 4; j++) S[i][j] = av[i] * bw[j] + kcv[j];
        }
        #pragma unroll
        for (int kk = 1; kk < 11; kk++) {
            float4 a4 = *(const float4*)&Qs[kk][ty * 4];
            float4 b4 = *(const float4*)&Ks[cur][kk][tx * 4];
            float av[4] = {a4.x, a4.y, a4.z, a4.w};
            float bw[4] = {b4.x, b4.y, b4.z, b4.w};
            #pragma unroll
            for (int i = 0; i < 4; i++)
                #pragma unroll
                for (int j = 0; j < 4; j++) S[i][j] += av[i] * bw[j];
        }

        // ---- + log2(pi) (in-loop MUFU.LG2), exp2, accumulate l ----
        {
            float pr[4][4] = {{lg2p(pv0.x), lg2p(pv0.y), lg2p(pv0.z), lg2p(pv0.w)},
                              {lg2p(pv1.x), lg2p(pv1.y), lg2p(pv1.z), lg2p(pv1.w)},
                              {lg2p(pv2.x), lg2p(pv2.y), lg2p(pv2.z), lg2p(pv2.w)},
                              {lg2p(pv3.x), lg2p(pv3.y), lg2p(pv3.z), lg2p(pv3.w)}};
            #pragma unroll
            for (int i = 0; i < 4; i++) {
                #pragma unroll
                for (int j = 0; j < 4; j++) {
                    S[i][j] = ex2f(S[i][j] + pr[i][j]);
                    l[i] += S[i][j];
                }
            }
        }

        // ---- PV: O += P . v_raw  (V tile == K tile rows 0..10) ----
        #pragma unroll
        for (int c = 0; c < 11; c++) {
            float4 v4 = *(const float4*)&Ks[cur][c][tx * 4];
            float vv[4] = {v4.x, v4.y, v4.z, v4.w};
            #pragma unroll
            for (int i = 0; i < 4; i++) {
                O[i][c] += S[i][0] * vv[0] + S[i][1] * vv[1]
                         + S[i][2] * vv[2] + S[i][3] * vv[3];
            }
        }

        __syncthreads();
    }

    // ---- reduce across the 16 tx lanes, normalize, store ----
    #pragma unroll
    for (int i = 0; i < 4; i++) {
        l[i] += __shfl_xor_sync(0xffffffffu, l[i], 1);
        l[i] += __shfl_xor_sync(0xffffffffu, l[i], 2);
        l[i] += __shfl_xor_sync(0xffffffffu, l[i], 4);
        l[i] += __shfl_xor_sync(0xffffffffu, l[i], 8);
        #pragma unroll
        for (int c = 0; c < 11; c++) {
            O[i][c] += __shfl_xor_sync(0xffffffffu, O[i][c], 1);
            O[i][c] += __shfl_xor_sync(0xffffffffu, O[i][c], 2);
            O[i][c] += __shfl_xor_sync(0xffffffffu, O[i][c], 4);
            O[i][c] += __shfl_xor_sync(0xffffffffu, O[i][c], 8);
        }
    }

    if (tx == 0) {
        #pragma unroll
        for (int i = 0; i < 4; i++) {
            float inv = 1.0f / l[i];
            size_t base = ((size_t)(b * LQ + q0 + ty * 4 + i)) * 88 + h * 11;
            #pragma unroll
            for (int c = 0; c < 11; c++) g_cr[base + c] = O[i][c] * inv;
        }
    }
}

// ---------------- epilogue: out = ctxRaw(4096x88) @ R(88x256) + obias ----------------
__global__ void __launch_bounds__(256)
epilogue_kernel(float* __restrict__ out)
{
    __shared__ float crsT[88][32];
    int t = threadIdx.x;
    int row0 = blockIdx.x * 32;

    for (int i = t; i < 32 * 88; i += 256) {
        int r = i / 88, j = i % 88;
        crsT[j][r] = g_cr[(size_t)(row0 + r) * 88 + j];
    }
    __syncthreads();

    float acc[32];
    #pragma unroll
    for (int r = 0; r < 32; r++) acc[r] = 0.f;

    #pragma unroll 4
    for (int j = 0; j < 88; j++) {
        float rv = g_R[j * HID + t];
        #pragma unroll
        for (int r = 0; r < 32; r += 4) {
            float4 cv = *(const float4*)&crsT[j][r];
            acc[r]     += cv.x * rv;
            acc[r + 1] += cv.y * rv;
            acc[r + 2] += cv.z * rv;
            acc[r + 3] += cv.w * rv;
        }
    }

    float ob = g_obias[t];
    for (int r = 0; r < 32; r++)
        out[(size_t)(row0 + r) * HID + t] = acc[r] + ob;
}

// ---------------- launch ----------------
extern "C" void kernel_launch(void* const* d_in, const int* in_sizes, int n_in,
                              void* d_out, int out_size)
{
    const float* q_fp  = (const float*)d_in[0];
    const float* v_ret = (const float*)d_in[1];
    const float* pi    = (const float*)d_in[2];
    const float* Wq_s  = (const float*)d_in[3];
    const float* bq_s  = (const float*)d_in[4];
    const float* Wk_s  = (const float*)d_in[5];
    const float* bk_s  = (const float*)d_in[6];
    const float* Wq_w  = (const float*)d_in[7];
    const float* bq_w  = (const float*)d_in[8];
    const float* Wk_w  = (const float*)d_in[9];
    const float* bk_w  = (const float*)d_in[10];
    const float* Wv    = (const float*)d_in[11];
    const float* bv    = (const float*)d_in[12];
    const float* Wo    = (const float*)d_in[13];
    const float* bo    = (const float*)d_in[14];
    const float* wb    = (const float*)d_in[15];
    float* out = (float*)d_out;

    p0_params<<<H_ + 1, 256>>>(Wq_s, bq_s, Wk_s, bk_s, Wq_w, bq_w, Wk_w, bk_w,
                               Wv, bv, Wo, bo, wb);
    dim3 gq((B_ * LQ) / 128, H_);
    p1_q<<<gq, 128>>>(q_fp);
    dim3 gk((B_ * LK) / 128, H_);
    p1_k<<<gk, 128>>>(v_ret, Wk_w, bk_w, wb);
    dim3 g(H_, LQ / 64, B_);
    attn_kernel<<<g, 256>>>(pi);
    epilogue_kernel<<<(B_ * LQ) / 32, 256>>>(out);
}

// round 12
// speedup vs baseline: 1.6602x; 1.1436x over previous
#include <cuda_runtime.h>
#include <math.h>

#define B_   4
#define LQ   1024
#define LK   2048
#define H_   8
#define HID  256
#define D_   32
#define TEMP_INV 10.0f
#define LOG2E 1.4426950408889634f

// ---------------- scratch (device globals; no allocations) ----------------
__device__ float g_G[H_ * 12 * 12];                 // per-head bilinear form (LOG2E-scaled)
__device__ float g_R[88 * HID];                     // fused Av_h @ Wo_h^T
__device__ float g_obias_part[H_][HID];             // per-head partial of bo + bv @ Wo^T
__device__ float g_Q[(size_t)B_ * H_ * 11 * LQ];    // Q-hat transposed [bh][c][q], c=0..10
__device__ float g_Kraw[(size_t)B_ * 11 * LK];      // raw key features transposed [b][j][k]
__device__ float g_kc[(size_t)B_ * H_ * LK];        // -beta*kn*LOG2E per head
__device__ float g_cr[(size_t)B_ * LQ * 88];        // ctxRaw

__device__ __forceinline__ float sigmoidf_(float x) { return 1.f / (1.f + expf(-x)); }

__device__ __forceinline__ float ex2f(float x) {
    float r;
    asm("ex2.approx.ftz.f32 %0, %1;" : "=f"(r) : "f"(x));
    return r;
}
__device__ __forceinline__ float lg2p(float x) {
    return __log2f(fmaxf(x, 1e-9f));
}

// ---------------- P0: fold weights into G_h, R, obias partials (head-parallel) ----------------
__global__ void p0_params(const float* __restrict__ Wq_s, const float* __restrict__ bq_s,
                          const float* __restrict__ Wk_s, const float* __restrict__ bk_s,
                          const float* __restrict__ Wq_w, const float* __restrict__ bq_w,
                          const float* __restrict__ Wk_w, const float* __restrict__ bk_w,
                          const float* __restrict__ Wv,   const float* __restrict__ bv,
                          const float* __restrict__ Wo,   const float* __restrict__ bo,
                          const float* __restrict__ wb)
{
    int t = threadIdx.x;
    int h = blockIdx.x;
    float alpha = sigmoidf_(wb[0]);
    float c1 = (1.f - alpha) / sqrtf((float)D_) * LOG2E;
    float c2 = 2.f * alpha * TEMP_INV * LOG2E;

    if (t < 144) {
        int r = t / 12, c = t % 12;
        float acc = 0.f;
        if (r < 8 && c < 8) {
            for (int d = 0; d < 32; d++) acc += Wq_s[(h*32+d)*8 + r] * Wk_s[(h*32+d)*8 + c];
            acc *= c1;
        } else if (r < 8 && c == 11) {
            for (int d = 0; d < 32; d++) acc += Wq_s[(h*32+d)*8 + r] * bk_s[h*32+d];
            acc *= c1;
        } else if (r >= 8 && r < 11 && c >= 8 && c < 11) {
            for (int d = 0; d < 32; d++) acc += Wq_w[(h*32+d)*3 + (r-8)] * Wk_w[(h*32+d)*3 + (c-8)];
            acc *= c2;
        } else if (r >= 8 && r < 11 && c == 11) {
            for (int d = 0; d < 32; d++) acc += Wq_w[(h*32+d)*3 + (r-8)] * bk_w[h*32+d];
            acc *= c2;
        } else if (r == 11 && c < 8) {
            for (int d = 0; d < 32; d++) acc += bq_s[h*32+d] * Wk_s[(h*32+d)*8 + c];
            acc *= c1;
        } else if (r == 11 && c >= 8 && c < 11) {
            for (int d = 0; d < 32; d++) acc += bq_w[h*32+d] * Wk_w[(h*32+d)*3 + (c-8)];
            acc *= c2;
        } else if (r == 11 && c == 11) {
            float a1 = 0.f, a2 = 0.f;
            for (int d = 0; d < 32; d++) {
                a1 += bq_s[h*32+d] * bk_s[h*32+d];
                a2 += bq_w[h*32+d] * bk_w[h*32+d];
            }
            acc = c1 * a1 + c2 * a2;
        }
        g_G[(h*12 + r)*12 + c] = acc;
    }
    // wo row reused for BOTH the R fold and the obias partial (removes the serial obias block)
    float wo[32];
    #pragma unroll
    for (int d = 0; d < 32; d++) wo[d] = Wo[t * HID + h*32 + d];
    for (int j = 0; j < 11; j++) {
        float acc = 0.f;
        #pragma unroll
        for (int d = 0; d < 32; d++) acc += Wv[(h*32+d)*11 + j] * wo[d];
        g_R[(h*11 + j) * HID + t] = acc;
    }
    {
        float p = (h == 0) ? bo[t] : 0.f;
        #pragma unroll
        for (int d = 0; d < 32; d++) p += bv[h*32 + d] * wo[d];
        g_obias_part[h][t] = p;
    }
}

// ---------------- P1q: build Q-hat, head-parallel (blockIdx.y = h) ----------------
__global__ void __launch_bounds__(128)
p1_q(const float* __restrict__ q_fp)
{
    __shared__ float Gs[144];
    int t = threadIdx.x;
    int h = blockIdx.y;
    for (int i = t; i < 144; i += 128) Gs[i] = g_G[h * 144 + i];
    __syncthreads();

    int idx = blockIdx.x * 128 + t;   // b*LQ + q
    int b = idx >> 10, q = idx & (LQ - 1);

    float x[11];
    #pragma unroll
    for (int j = 0; j < 11; j++) x[j] = q_fp[(size_t)idx * 11 + j];

    size_t base = ((size_t)(b * H_ + h) * 11) * LQ + q;
    #pragma unroll
    for (int c = 0; c < 11; c++) {
        float a = Gs[11*12 + c];
        #pragma unroll
        for (int r = 0; r < 11; r++) a += x[r] * Gs[r*12 + c];
        g_Q[base + (size_t)c * LQ] = a;
    }
}

// ---------------- P1k: raw K features + per-head kn, head-parallel (blockIdx.y = h) ----------------
__global__ void __launch_bounds__(128)
p1_k(const float* __restrict__ v_ret, const float* __restrict__ Wk_w,
     const float* __restrict__ bk_w, const float* __restrict__ wb)
{
    __shared__ float Ws[D_ * 3];
    __shared__ float Bs[D_];
    int t = threadIdx.x;
    int h = blockIdx.y;
    if (t < D_ * 3) Ws[t] = Wk_w[h * D_ * 3 + t];
    if (t < D_)     Bs[t] = bk_w[h * D_ + t];
    __syncthreads();

    float alpha = sigmoidf_(wb[0]);
    float beta2 = alpha * TEMP_INV * LOG2E;
    int idx = blockIdx.x * 128 + t;   // b*LK + k
    int b = idx >> 11, k = idx & (LK - 1);

    float x3[3];
    #pragma unroll
    for (int j = 0; j < 3; j++) x3[j] = v_ret[(size_t)idx * 11 + 8 + j];

    if (h == 0) {
        #pragma unroll
        for (int j = 0; j < 11; j++)
            g_Kraw[((size_t)b * 11 + j) * LK + k] = v_ret[(size_t)idx * 11 + j];
    }

    float kn = 0.f;
    #pragma unroll 4
    for (int d = 0; d < D_; d++) {
        float s = Bs[d];
        s += x3[0] * Ws[d*3 + 0];
        s += x3[1] * Ws[d*3 + 1];
        s += x3[2] * Ws[d*3 + 2];
        kn += s * s;
    }
    g_kc[(size_t)(b * H_ + h) * LK + k] = -beta2 * kn;
}

// ---------------- main attention kernel: R11-frozen (fused log2(pi)) ----------------
// 256 threads = 16 tx (4 keys) x 16 ty (4 rows). BM=BN=64. Double-buffered K tile.
__global__ void __launch_bounds__(256, 2)
attn_kernel(const float* __restrict__ pi)
{
    __shared__ float Qs[11][64];        // Q-tilde rows 0..10
    __shared__ float Ks[2][12][64];     // rows 0..10: raw key feats (= V), row 11: kc

    int t = threadIdx.x;
    int tx = t & 15, ty = t >> 4;
    int h = blockIdx.x, qt = blockIdx.y, b = blockIdx.z;
    int bh = b * H_ + h;
    int q0 = qt * 64;

    if (t < 176) {
        int c = t >> 4, col4 = (t & 15) * 4;
        *(float4*)&Qs[c][col4] =
            *(const float4*)&g_Q[((size_t)bh * 11 + c) * LQ + q0 + col4];
    }
    if (t < 192) {
        int c = t >> 4, col4 = (t & 15) * 4;
        const float* src = (c < 11)
            ? &g_Kraw[((size_t)b * 11 + c) * LK + col4]
            : &g_kc[(size_t)bh * LK + col4];
        *(float4*)&Ks[0][c][col4] = *(const float4*)src;
    }

    float O[4][11];
    float l[4];
    #pragma unroll
    for (int i = 0; i < 4; i++) {
        l[i] = 0.f;
        #pragma unroll
        for (int c = 0; c < 11; c++) O[i][c] = 0.f;
    }

    const float* piP = pi + ((size_t)(b * LQ + q0 + ty * 4)) * LK + tx * 4;

    __syncthreads();

    for (int kt = 0; kt < 32; kt++) {
        int cur = kt & 1;
        int k0 = kt * 64;

        // prefetch pi tile (fp32, L2-resident across the 8 heads; consumed after QK)
        float4 pv0 = *(const float4*)(piP + k0);
        float4 pv1 = *(const float4*)(piP + (size_t)LK + k0);
        float4 pv2 = *(const float4*)(piP + (size_t)2 * LK + k0);
        float4 pv3 = *(const float4*)(piP + (size_t)3 * LK + k0);

        // stage next K tile into the other buffer
        if (kt < 31 && t < 192) {
            int c = t >> 4, col4 = (t & 15) * 4;
            const float* src = (c < 11)
                ? &g_Kraw[((size_t)b * 11 + c) * LK + k0 + 64 + col4]
                : &g_kc[(size_t)bh * LK + k0 + 64 + col4];
            *(float4*)&Ks[cur ^ 1][c][col4] = *(const float4*)src;
        }

        // ---- QK: S = Qt . k_raw  (inner dim 11), kc folded into first FMA ----
        float S[4][4];
        {
            float4 kc4 = *(const float4*)&Ks[cur][11][tx * 4];
            float kcv[4] = {kc4.x, kc4.y, kc4.z, kc4.w};
            float4 a4 = *(const float4*)&Qs[0][ty * 4];
            float4 b4 = *(const float4*)&Ks[cur][0][tx * 4];
            float av[4] = {a4.x, a4.y, a4.z, a4.w};
            float bw[4] = {b4.x, b4.y, b4.z, b4.w};
            #pragma unroll
            for (int i = 0; i < 4; i++)
                #pragma unroll
                for (int j = 0; j < 4; j++) S[i][j] = av[i] * bw[j] + kcv[j];
        }
        #pragma unroll
        for (int kk = 1; kk < 11; kk++) {
            float4 a4 = *(const float4*)&Qs[kk][ty * 4];
            float4 b4 = *(const float4*)&Ks[cur][kk][tx * 4];
            float av[4] = {a4.x, a4.y, a4.z, a4.w};
            float bw[4] = {b4.x, b4.y, b4.z, b4.w};
            #pragma unroll
            for (int i = 0; i < 4; i++)
                #pragma unroll
                for (int j = 0; j < 4; j++) S[i][j] += av[i] * bw[j];
        }

        // ---- + log2(pi) (in-loop MUFU.LG2), exp2, accumulate l ----
        {
            float pr[4][4] = {{lg2p(pv0.x), lg2p(pv0.y), lg2p(pv0.z), lg2p(pv0.w)},
                              {lg2p(pv1.x), lg2p(pv1.y), lg2p(pv1.z), lg2p(pv1.w)},
                              {lg2p(pv2.x), lg2p(pv2.y), lg2p(pv2.z), lg2p(pv2.w)},
                              {lg2p(pv3.x), lg2p(pv3.y), lg2p(pv3.z), lg2p(pv3.w)}};
            #pragma unroll
            for (int i = 0; i < 4; i++) {
                #pragma unroll
                for (int j = 0; j < 4; j++) {
                    S[i][j] = ex2f(S[i][j] + pr[i][j]);
                    l[i] += S[i][j];
                }
            }
        }

        // ---- PV: O += P . v_raw  (V tile == K tile rows 0..10) ----
        #pragma unroll
        for (int c = 0; c < 11; c++) {
            float4 v4 = *(const float4*)&Ks[cur][c][tx * 4];
            float vv[4] = {v4.x, v4.y, v4.z, v4.w};
            #pragma unroll
            for (int i = 0; i < 4; i++) {
                O[i][c] += S[i][0] * vv[0] + S[i][1] * vv[1]
                         + S[i][2] * vv[2] + S[i][3] * vv[3];
            }
        }

        __syncthreads();
    }

    // ---- reduce across the 16 tx lanes, normalize, store ----
    #pragma unroll
    for (int i = 0; i < 4; i++) {
        l[i] += __shfl_xor_sync(0xffffffffu, l[i], 1);
        l[i] += __shfl_xor_sync(0xffffffffu, l[i], 2);
        l[i] += __shfl_xor_sync(0xffffffffu, l[i], 4);
        l[i] += __shfl_xor_sync(0xffffffffu, l[i], 8);
        #pragma unroll
        for (int c = 0; c < 11; c++) {
            O[i][c] += __shfl_xor_sync(0xffffffffu, O[i][c], 1);
            O[i][c] += __shfl_xor_sync(0xffffffffu, O[i][c], 2);
            O[i][c] += __shfl_xor_sync(0xffffffffu, O[i][c], 4);
            O[i][c] += __shfl_xor_sync(0xffffffffu, O[i][c], 8);
        }
    }

    if (tx == 0) {
        #pragma unroll
        for (int i = 0; i < 4; i++) {
            float inv = 1.0f / l[i];
            size_t base = ((size_t)(b * LQ + q0 + ty * 4 + i)) * 88 + h * 11;
            #pragma unroll
            for (int c = 0; c < 11; c++) g_cr[base + c] = O[i][c] * inv;
        }
    }
}

// ---------------- epilogue: out = ctxRaw(4096x88) @ R(88x256) + obias ----------------
// R staged through shared in 4 chunks of 22 rows (coalesced, once per CTA).
__global__ void __launch_bounds__(256)
epilogue_kernel(float* __restrict__ out)
{
    __shared__ float crsT[88][32];
    __shared__ float Rs[22][HID];
    int t = threadIdx.x;
    int row0 = blockIdx.x * 32;

    for (int i = t; i < 32 * 88; i += 256) {
        int r = i / 88, j = i % 88;
        crsT[j][r] = g_cr[(size_t)(row0 + r) * 88 + j];
    }

    float acc[32];
    #pragma unroll
    for (int r = 0; r < 32; r++) acc[r] = 0.f;

    for (int jc = 0; jc < 4; jc++) {
        __syncthreads();
        {
            const float4* src = (const float4*)&g_R[jc * 22 * HID];
            float4* dst = (float4*)&Rs[0][0];
            for (int i = t; i < 22 * (HID / 4); i += 256) dst[i] = src[i];
        }
        __syncthreads();
        #pragma unroll 2
        for (int jj = 0; jj < 22; jj++) {
            int j = jc * 22 + jj;
            float rv = Rs[jj][t];
            #pragma unroll
            for (int r = 0; r < 32; r += 4) {
                float4 cv = *(const float4*)&crsT[j][r];
                acc[r]     += cv.x * rv;
                acc[r + 1] += cv.y * rv;
                acc[r + 2] += cv.z * rv;
                acc[r + 3] += cv.w * rv;
            }
        }
    }

    float ob = 0.f;
    #pragma unroll
    for (int hh = 0; hh < H_; hh++) ob += g_obias_part[hh][t];

    for (int r = 0; r < 32; r++)
        out[(size_t)(row0 + r) * HID + t] = acc[r] + ob;
}

// ---------------- launch ----------------
extern "C" void kernel_launch(void* const* d_in, const int* in_sizes, int n_in,
                              void* d_out, int out_size)
{
    const float* q_fp  = (const float*)d_in[0];
    const float* v_ret = (const float*)d_in[1];
    const float* pi    = (const float*)d_in[2];
    const float* Wq_s  = (const float*)d_in[3];
    const float* bq_s  = (const float*)d_in[4];
    const float* Wk_s  = (const float*)d_in[5];
    const float* bk_s  = (const float*)d_in[6];
    const float* Wq_w  = (const float*)d_in[7];
    const float* bq_w  = (const float*)d_in[8];
    const float* Wk_w  = (const float*)d_in[9];
    const float* bk_w  = (const float*)d_in[10];
    const float* Wv    = (const float*)d_in[11];
    const float* bv    = (const float*)d_in[12];
    const float* Wo    = (const float*)d_in[13];
    const float* bo    = (const float*)d_in[14];
    const float* wb    = (const float*)d_in[15];
    float* out = (float*)d_out;

    p0_params<<<H_, 256>>>(Wq_s, bq_s, Wk_s, bk_s, Wq_w, bq_w, Wk_w, bk_w,
                           Wv, bv, Wo, bo, wb);
    dim3 gq((B_ * LQ) / 128, H_);
    p1_q<<<gq, 128>>>(q_fp);
    dim3 gk((B_ * LK) / 128, H_);
    p1_k<<<gk, 128>>>(v_ret, Wk_w, bk_w, wb);
    dim3 g(H_, LQ / 64, B_);
    attn_kernel<<<g, 256>>>(pi);
    epilogue_kernel<<<(B_ * LQ) / 32, 256>>>(out);
}

// round 13
// speedup vs baseline: 1.7286x; 1.0412x over previous
#include <cuda_runtime.h>
#include <math.h>

#define B_   4
#define LQ   1024
#define LK   2048
#define H_   8
#define HID  256
#define D_   32
#define TEMP_INV 10.0f
#define LOG2E 1.4426950408889634f

// ---------------- scratch (device globals; no allocations) ----------------
__device__ float g_G[H_ * 12 * 12];                 // per-head bilinear form (LOG2E-scaled)
__device__ float g_R[88 * HID];                     // fused Av_h @ Wo_h^T
__device__ float g_obias_part[H_][HID];             // per-head partial of bo + bv @ Wo^T
__device__ float g_Q[(size_t)B_ * H_ * 11 * LQ];    // Q-hat transposed [bh][c][q], c=0..10
__device__ float g_Kraw[(size_t)B_ * 11 * LK];      // raw key features transposed [b][j][k]
__device__ float g_kc[(size_t)B_ * H_ * LK];        // -beta*kn*LOG2E per head
__device__ float g_cr[(size_t)B_ * LQ * 88];        // ctxRaw

__device__ __forceinline__ float sigmoidf_(float x) { return 1.f / (1.f + expf(-x)); }

__device__ __forceinline__ float ex2f(float x) {
    float r;
    asm("ex2.approx.ftz.f32 %0, %1;" : "=f"(r) : "f"(x));
    return r;
}

// ---------------- P0: fold weights into G_h, R, obias partials (head-parallel) ----------------
__global__ void p0_params(const float* __restrict__ Wq_s, const float* __restrict__ bq_s,
                          const float* __restrict__ Wk_s, const float* __restrict__ bk_s,
                          const float* __restrict__ Wq_w, const float* __restrict__ bq_w,
                          const float* __restrict__ Wk_w, const float* __restrict__ bk_w,
                          const float* __restrict__ Wv,   const float* __restrict__ bv,
                          const float* __restrict__ Wo,   const float* __restrict__ bo,
                          const float* __restrict__ wb)
{
    int t = threadIdx.x;
    int h = blockIdx.x;
    float alpha = sigmoidf_(wb[0]);
    float c1 = (1.f - alpha) / sqrtf((float)D_) * LOG2E;
    float c2 = 2.f * alpha * TEMP_INV * LOG2E;

    if (t < 144) {
        int r = t / 12, c = t % 12;
        float acc = 0.f;
        if (r < 8 && c < 8) {
            for (int d = 0; d < 32; d++) acc += Wq_s[(h*32+d)*8 + r] * Wk_s[(h*32+d)*8 + c];
            acc *= c1;
        } else if (r < 8 && c == 11) {
            for (int d = 0; d < 32; d++) acc += Wq_s[(h*32+d)*8 + r] * bk_s[h*32+d];
            acc *= c1;
        } else if (r >= 8 && r < 11 && c >= 8 && c < 11) {
            for (int d = 0; d < 32; d++) acc += Wq_w[(h*32+d)*3 + (r-8)] * Wk_w[(h*32+d)*3 + (c-8)];
            acc *= c2;
        } else if (r >= 8 && r < 11 && c == 11) {
            for (int d = 0; d < 32; d++) acc += Wq_w[(h*32+d)*3 + (r-8)] * bk_w[h*32+d];
            acc *= c2;
        } else if (r == 11 && c < 8) {
            for (int d = 0; d < 32; d++) acc += bq_s[h*32+d] * Wk_s[(h*32+d)*8 + c];
            acc *= c1;
        } else if (r == 11 && c >= 8 && c < 11) {
            for (int d = 0; d < 32; d++) acc += bq_w[h*32+d] * Wk_w[(h*32+d)*3 + (c-8)];
            acc *= c2;
        } else if (r == 11 && c == 11) {
            float a1 = 0.f, a2 = 0.f;
            for (int d = 0; d < 32; d++) {
                a1 += bq_s[h*32+d] * bk_s[h*32+d];
                a2 += bq_w[h*32+d] * bk_w[h*32+d];
            }
            acc = c1 * a1 + c2 * a2;
        }
        g_G[(h*12 + r)*12 + c] = acc;
    }
    float wo[32];
    #pragma unroll
    for (int d = 0; d < 32; d++) wo[d] = Wo[t * HID + h*32 + d];
    for (int j = 0; j < 11; j++) {
        float acc = 0.f;
        #pragma unroll
        for (int d = 0; d < 32; d++) acc += Wv[(h*32+d)*11 + j] * wo[d];
        g_R[(h*11 + j) * HID + t] = acc;
    }
    {
        float p = (h == 0) ? bo[t] : 0.f;
        #pragma unroll
        for (int d = 0; d < 32; d++) p += bv[h*32 + d] * wo[d];
        g_obias_part[h][t] = p;
    }
}

// ---------------- P1q: build Q-hat, head-parallel (blockIdx.y = h) ----------------
__global__ void __launch_bounds__(128)
p1_q(const float* __restrict__ q_fp)
{
    __shared__ float Gs[144];
    int t = threadIdx.x;
    int h = blockIdx.y;
    for (int i = t; i < 144; i += 128) Gs[i] = g_G[h * 144 + i];
    __syncthreads();

    int idx = blockIdx.x * 128 + t;   // b*LQ + q
    int b = idx >> 10, q = idx & (LQ - 1);

    float x[11];
    #pragma unroll
    for (int j = 0; j < 11; j++) x[j] = q_fp[(size_t)idx * 11 + j];

    size_t base = ((size_t)(b * H_ + h) * 11) * LQ + q;
    #pragma unroll
    for (int c = 0; c < 11; c++) {
        float a = Gs[11*12 + c];
        #pragma unroll
        for (int r = 0; r < 11; r++) a += x[r] * Gs[r*12 + c];
        g_Q[base + (size_t)c * LQ] = a;
    }
}

// ---------------- P1k: raw K features + per-head kn, head-parallel (blockIdx.y = h) ----------------
__global__ void __launch_bounds__(128)
p1_k(const float* __restrict__ v_ret, const float* __restrict__ Wk_w,
     const float* __restrict__ bk_w, const float* __restrict__ wb)
{
    __shared__ float Ws[D_ * 3];
    __shared__ float Bs[D_];
    int t = threadIdx.x;
    int h = blockIdx.y;
    if (t < D_ * 3) Ws[t] = Wk_w[h * D_ * 3 + t];
    if (t < D_)     Bs[t] = bk_w[h * D_ + t];
    __syncthreads();

    float alpha = sigmoidf_(wb[0]);
    float beta2 = alpha * TEMP_INV * LOG2E;
    int idx = blockIdx.x * 128 + t;   // b*LK + k
    int b = idx >> 11, k = idx & (LK - 1);

    float x3[3];
    #pragma unroll
    for (int j = 0; j < 3; j++) x3[j] = v_ret[(size_t)idx * 11 + 8 + j];

    if (h == 0) {
        #pragma unroll
        for (int j = 0; j < 11; j++)
            g_Kraw[((size_t)b * 11 + j) * LK + k] = v_ret[(size_t)idx * 11 + j];
    }

    float kn = 0.f;
    #pragma unroll 4
    for (int d = 0; d < D_; d++) {
        float s = Bs[d];
        s += x3[0] * Ws[d*3 + 0];
        s += x3[1] * Ws[d*3 + 1];
        s += x3[2] * Ws[d*3 + 2];
        kn += s * s;
    }
    g_kc[(size_t)(b * H_ + h) * LK + k] = -beta2 * kn;
}

// ---------------- main attention kernel: P = pi * exp2(S + kc) — no log, one FMUL ----------------
// 256 threads = 16 tx (4 keys) x 16 ty (4 rows). BM=BN=64. Double-buffered K tile.
__global__ void __launch_bounds__(256, 2)
attn_kernel(const float* __restrict__ pi)
{
    __shared__ float Qs[11][64];        // Q-tilde rows 0..10
    __shared__ float Ks[2][12][64];     // rows 0..10: raw key feats (= V), row 11: kc

    int t = threadIdx.x;
    int tx = t & 15, ty = t >> 4;
    int h = blockIdx.x, qt = blockIdx.y, b = blockIdx.z;
    int bh = b * H_ + h;
    int q0 = qt * 64;

    if (t < 176) {
        int c = t >> 4, col4 = (t & 15) * 4;
        *(float4*)&Qs[c][col4] =
            *(const float4*)&g_Q[((size_t)bh * 11 + c) * LQ + q0 + col4];
    }
    if (t < 192) {
        int c = t >> 4, col4 = (t & 15) * 4;
        const float* src = (c < 11)
            ? &g_Kraw[((size_t)b * 11 + c) * LK + col4]
            : &g_kc[(size_t)bh * LK + col4];
        *(float4*)&Ks[0][c][col4] = *(const float4*)src;
    }

    float O[4][11];
    float l[4];
    #pragma unroll
    for (int i = 0; i < 4; i++) {
        l[i] = 0.f;
        #pragma unroll
        for (int c = 0; c < 11; c++) O[i][c] = 0.f;
    }

    const float* piP = pi + ((size_t)(b * LQ + q0 + ty * 4)) * LK + tx * 4;

    __syncthreads();

    for (int kt = 0; kt < 32; kt++) {
        int cur = kt & 1;
        int k0 = kt * 64;

        // prefetch pi tile (fp32, L2-resident across the 8 heads; consumed after QK)
        float4 pv0 = *(const float4*)(piP + k0);
        float4 pv1 = *(const float4*)(piP + (size_t)LK + k0);
        float4 pv2 = *(const float4*)(piP + (size_t)2 * LK + k0);
        float4 pv3 = *(const float4*)(piP + (size_t)3 * LK + k0);

        // stage next K tile into the other buffer
        if (kt < 31 && t < 192) {
            int c = t >> 4, col4 = (t & 15) * 4;
            const float* src = (c < 11)
                ? &g_Kraw[((size_t)b * 11 + c) * LK + k0 + 64 + col4]
                : &g_kc[(size_t)bh * LK + k0 + 64 + col4];
            *(float4*)&Ks[cur ^ 1][c][col4] = *(const float4*)src;
        }

        // ---- QK: S = Qt . k_raw  (inner dim 11), kc folded into first FMA ----
        float S[4][4];
        {
            float4 kc4 = *(const float4*)&Ks[cur][11][tx * 4];
            float kcv[4] = {kc4.x, kc4.y, kc4.z, kc4.w};
            float4 a4 = *(const float4*)&Qs[0][ty * 4];
            float4 b4 = *(const float4*)&Ks[cur][0][tx * 4];
            float av[4] = {a4.x, a4.y, a4.z, a4.w};
            float bw[4] = {b4.x, b4.y, b4.z, b4.w};
            #pragma unroll
            for (int i = 0; i < 4; i++)
                #pragma unroll
                for (int j = 0; j < 4; j++) S[i][j] = av[i] * bw[j] + kcv[j];
        }
        #pragma unroll
        for (int kk = 1; kk < 11; kk++) {
            float4 a4 = *(const float4*)&Qs[kk][ty * 4];
            float4 b4 = *(const float4*)&Ks[cur][kk][tx * 4];
            float av[4] = {a4.x, a4.y, a4.z, a4.w};
            float bw[4] = {b4.x, b4.y, b4.z, b4.w};
            #pragma unroll
            for (int i = 0; i < 4; i++)
                #pragma unroll
                for (int j = 0; j < 4; j++) S[i][j] += av[i] * bw[j];
        }

        // ---- P = pi * exp2(S)  (log->exp round-trip on pi removed; exact identity) ----
        {
            float pr[4][4] = {{pv0.x, pv0.y, pv0.z, pv0.w},
                              {pv1.x, pv1.y, pv1.z, pv1.w},
                              {pv2.x, pv2.y, pv2.z, pv2.w},
                              {pv3.x, pv3.y, pv3.z, pv3.w}};
            #pragma unroll
            for (int i = 0; i < 4; i++) {
                #pragma unroll
                for (int j = 0; j < 4; j++) {
                    S[i][j] = ex2f(S[i][j]) * pr[i][j];
                    l[i] += S[i][j];
                }
            }
        }

        // ---- PV: O += P . v_raw  (V tile == K tile rows 0..10) ----
        #pragma unroll
        for (int c = 0; c < 11; c++) {
            float4 v4 = *(const float4*)&Ks[cur][c][tx * 4];
            float vv[4] = {v4.x, v4.y, v4.z, v4.w};
            #pragma unroll
            for (int i = 0; i < 4; i++) {
                O[i][c] += S[i][0] * vv[0] + S[i][1] * vv[1]
                         + S[i][2] * vv[2] + S[i][3] * vv[3];
            }
        }

        __syncthreads();
    }

    // ---- reduce across the 16 tx lanes, normalize, store ----
    #pragma unroll
    for (int i = 0; i < 4; i++) {
        l[i] += __shfl_xor_sync(0xffffffffu, l[i], 1);
        l[i] += __shfl_xor_sync(0xffffffffu, l[i], 2);
        l[i] += __shfl_xor_sync(0xffffffffu, l[i], 4);
        l[i] += __shfl_xor_sync(0xffffffffu, l[i], 8);
        #pragma unroll
        for (int c = 0; c < 11; c++) {
            O[i][c] += __shfl_xor_sync(0xffffffffu, O[i][c], 1);
            O[i][c] += __shfl_xor_sync(0xffffffffu, O[i][c], 2);
            O[i][c] += __shfl_xor_sync(0xffffffffu, O[i][c], 4);
            O[i][c] += __shfl_xor_sync(0xffffffffu, O[i][c], 8);
        }
    }

    if (tx == 0) {
        #pragma unroll
        for (int i = 0; i < 4; i++) {
            float inv = 1.0f / l[i];
            size_t base = ((size_t)(b * LQ + q0 + ty * 4 + i)) * 88 + h * 11;
            #pragma unroll
            for (int c = 0; c < 11; c++) g_cr[base + c] = O[i][c] * inv;
        }
    }
}

// ---------------- epilogue: out = ctxRaw(4096x88) @ R(88x256) + obias ----------------
// R staged through shared in 4 chunks of 22 rows (coalesced, once per CTA).
__global__ void __launch_bounds__(256)
epilogue_kernel(float* __restrict__ out)
{
    __shared__ float crsT[88][32];
    __shared__ float Rs[22][HID];
    int t = threadIdx.x;
    int row0 = blockIdx.x * 32;

    for (int i = t; i < 32 * 88; i += 256) {
        int r = i / 88, j = i % 88;
        crsT[j][r] = g_cr[(size_t)(row0 + r) * 88 + j];
    }

    float acc[32];
    #pragma unroll
    for (int r = 0; r < 32; r++) acc[r] = 0.f;

    for (int jc = 0; jc < 4; jc++) {
        __syncthreads();
        {
            const float4* src = (const float4*)&g_R[jc * 22 * HID];
            float4* dst = (float4*)&Rs[0][0];
            for (int i = t; i < 22 * (HID / 4); i += 256) dst[i] = src[i];
        }
        __syncthreads();
        #pragma unroll 2
        for (int jj = 0; jj < 22; jj++) {
            int j = jc * 22 + jj;
            float rv = Rs[jj][t];
            #pragma unroll
            for (int r = 0; r < 32; r += 4) {
                float4 cv = *(const float4*)&crsT[j][r];
                acc[r]     += cv.x * rv;
                acc[r + 1] += cv.y * rv;
                acc[r + 2] += cv.z * rv;
                acc[r + 3] += cv.w * rv;
            }
        }
    }

    float ob = 0.f;
    #pragma unroll
    for (int hh = 0; hh < H_; hh++) ob += g_obias_part[hh][t];

    for (int r = 0; r < 32; r++)
        out[(size_t)(row0 + r) * HID + t] = acc[r] + ob;
}

// ---------------- launch ----------------
extern "C" void kernel_launch(void* const* d_in, const int* in_sizes, int n_in,
                              void* d_out, int out_size)
{
    const float* q_fp  = (const float*)d_in[0];
    const float* v_ret = (const float*)d_in[1];
    const float* pi    = (const float*)d_in[2];
    const float* Wq_s  = (const float*)d_in[3];
    const float* bq_s  = (const float*)d_in[4];
    const float* Wk_s  = (const float*)d_in[5];
    const float* bk_s  = (const float*)d_in[6];
    const float* Wq_w  = (const float*)d_in[7];
    const float* bq_w  = (const float*)d_in[8];
    const float* Wk_w  = (const float*)d_in[9];
    const float* bk_w  = (const float*)d_in[10];
    const float* Wv    = (const float*)d_in[11];
    const float* bv    = (const float*)d_in[12];
    const float* Wo    = (const float*)d_in[13];
    const float* bo    = (const float*)d_in[14];
    const float* wb    = (const float*)d_in[15];
    float* out = (float*)d_out;

    p0_params<<<H_, 256>>>(Wq_s, bq_s, Wk_s, bk_s, Wq_w, bq_w, Wk_w, bk_w,
                           Wv, bv, Wo, bo, wb);
    dim3 gq((B_ * LQ) / 128, H_);
    p1_q<<<gq, 128>>>(q_fp);
    dim3 gk((B_ * LK) / 128, H_);
    p1_k<<<gk, 128>>>(v_ret, Wk_w, bk_w, wb);
    dim3 g(H_, LQ / 64, B_);
    attn_kernel<<<g, 256>>>(pi);
    epilogue_kernel<<<(B_ * LQ) / 32, 256>>>(out);
}